// round 8
// baseline (speedup 1.0000x reference)
#include <cuda_runtime.h>

// Problem constants
#define Bn 64
#define Tn 4096
#define Fn 128
#define Hn 512
#define On 10
#define DTc 0.1f

// 16 clusters x 8 CTAs; cluster owns 4 batch rows; CTA owns 64 H-columns.
// Weights register-resident (f32x2-packed). Per step: ONE tx-counted full-wait,
// ONE __syncthreads, 7 st.async pushes. Partial reduction is a 15-shuffle
// butterfly inside 16-lane groups (kg = tid&15) — no smem round trip, no empty
// barriers (backpressure is carried by the tx-counted data dependency).
#define CLUSTER 8
#define ROWSn 4
#define COLSn 64
#define KTOT 640           // Hn + Fn
#define NT 256
#define KEXT 40            // k-extent per thread
#define NKG 16
#define KP2 (KEXT / 2)

#define PEER_BYTES ((CLUSTER - 1) * ROWSn * COLSn * 4)   // 7168 B from 7 peers

// SMEM layout (floats)
#define OFF_V 0                            // double-buffered [s(512);x(128)] per row
#define SZ_V (2 * ROWSn * KTOT)            // 5120
#define OFF_MB (OFF_V + SZ_V)              // full0, full1 mbarriers (16 B)
#define SMEM_FLOATS (OFF_MB + 4)
#define SMEM_BYTES (SMEM_FLOATS * 4)

__device__ __forceinline__ unsigned smem_u32(const void* p) {
    return (unsigned)__cvta_generic_to_shared(p);
}

__device__ __forceinline__ void cluster_sync_all() {
    asm volatile("barrier.cluster.arrive.aligned;\n\t"
                 "barrier.cluster.wait.aligned;" ::: "memory");
}

__device__ __forceinline__ unsigned long long pack2(float lo, float hi) {
    unsigned long long p;
    asm("mov.b64 %0, {%1, %2};" : "=l"(p) : "f"(lo), "f"(hi));
    return p;
}

__device__ __forceinline__ void fma2(unsigned long long& acc,
                                     unsigned long long q,
                                     unsigned long long w) {
    asm("fma.rn.f32x2 %0, %1, %2, %0;" : "+l"(acc) : "l"(q), "l"(w));
}

__device__ __forceinline__ float sum2(unsigned long long p) {
    float lo, hi;
    asm("mov.b64 {%0, %1}, %2;" : "=f"(lo), "=f"(hi) : "l"(p));
    return lo + hi;
}

// ---- mbarrier helpers ----
__device__ __forceinline__ void mbar_init(unsigned a, unsigned cnt) {
    asm volatile("mbarrier.init.shared.b64 [%0], %1;" :: "r"(a), "r"(cnt) : "memory");
}
__device__ __forceinline__ void mbar_arrive_local(unsigned a) {
    asm volatile("mbarrier.arrive.shared.b64 _, [%0];" :: "r"(a) : "memory");
}
__device__ __forceinline__ void mbar_expect_tx(unsigned a, unsigned bytes) {
    asm volatile("mbarrier.arrive.expect_tx.shared.b64 _, [%0], %1;"
                 :: "r"(a), "r"(bytes) : "memory");
}
__device__ __forceinline__ void mbar_wait_parity(unsigned a, unsigned ph) {
    asm volatile(
        "{\n\t.reg .pred P1;\n\t"
        "WAIT_LOOP_%=:\n\t"
        "mbarrier.try_wait.parity.acquire.cta.shared::cta.b64 P1, [%0], %1, 0x989680;\n\t"
        "@P1 bra.uni WAIT_DONE_%=;\n\t"
        "bra.uni WAIT_LOOP_%=;\n\t"
        "WAIT_DONE_%=:\n\t}"
        :: "r"(a), "r"(ph) : "memory");
}
// store 4B into rank's smem, signaling rank's mbarrier with 4 tx bytes
__device__ __forceinline__ void st_async_remote(unsigned local_data_addr,
                                                unsigned local_mbar_addr,
                                                unsigned rank, float v) {
    asm volatile("{\n\t.reg .b32 ra, rb;\n\t"
                 "mapa.shared::cluster.u32 ra, %0, %2;\n\t"
                 "mapa.shared::cluster.u32 rb, %1, %2;\n\t"
                 "st.async.shared::cluster.mbarrier::complete_tx::bytes.f32 [ra], %3, [rb];\n\t}"
                 :: "r"(local_data_addr), "r"(local_mbar_addr), "r"(rank), "f"(v)
                 : "memory");
}

extern __shared__ float smem[];

__global__ void __launch_bounds__(NT, 1) __cluster_dims__(CLUSTER, 1, 1)
ctrnn_kernel(const float* __restrict__ x, const float* __restrict__ ic,
             const float* __restrict__ Win, const float* __restrict__ Wrec,
             const float* __restrict__ bias, const float* __restrict__ tau,
             const float* __restrict__ rw, const float* __restrict__ rb,
             float* __restrict__ out)
{
    const int tid = threadIdx.x;
    const int rank = (int)(blockIdx.x & (CLUSTER - 1));
    const int clid = (int)(blockIdx.x >> 3);
    const int hbase = rank * COLSn;
    const int rbase = clid * ROWSn;

    float* V = smem + OFF_V;     // 2 x [ROWSn][KTOT]
    const unsigned mb_full0 = smem_u32(smem + OFF_MB);
    const unsigned mb_full1 = mb_full0 + 8;

    // NEW mapping: 16-lane groups share cg; kg varies across lanes -> shuffle reduce
    const int kg = tid & 15;             // k-group 0..15 (lane&15)
    const int cg = tid >> 4;             // col-group 0..15 (4 cols)
    const int kbase = kg * KEXT;
    const int cbase = hbase + cg * 4;
    const int lane = tid & 31;

    // finalize mapping: lane g (=lane&15) of each group holds output (r=g>>2, c=g&3)
    const int fr  = (lane & 15) >> 2;
    const int fhh = cg * 4 + (lane & 3);

    // ---- register weight tile, k-pair packed: w2[kk2][c] = {W[k][c], W[k+1][c]} ----
    unsigned long long w2[KP2][4];
    #pragma unroll
    for (int kk2 = 0; kk2 < KP2; ++kk2) {
        const int k = kbase + 2 * kk2;
        const float* s0 = (k < Hn) ? (Wrec + (size_t)k * Hn + cbase)
                                   : (Win + (size_t)(k - Hn) * Hn + cbase);
        const float* s1 = (k + 1 < Hn) ? (Wrec + (size_t)(k + 1) * Hn + cbase)
                                       : (Win + (size_t)(k + 1 - Hn) * Hn + cbase);
        float4 a = *reinterpret_cast<const float4*>(s0);
        float4 b = *reinterpret_cast<const float4*>(s1);
        w2[kk2][0] = pack2(a.x, b.x);
        w2[kk2][1] = pack2(a.y, b.y);
        w2[kk2][2] = pack2(a.z, b.z);
        w2[kk2][3] = pack2(a.w, b.w);
    }
    const float bi  = bias[hbase + fhh];
    const float dti = DTc / tau[hbase + fhh];

    if (tid == 0) {
        mbar_init(mb_full0, 1);
        mbar_init(mb_full1, 1);
        asm volatile("fence.mbarrier_init.release.cluster;" ::: "memory");
    }
    // init state buffer 0 with trainable IC (full s vector, locally)
    for (int i = tid; i < ROWSn * Hn; i += NT) {
        int r = i >> 9, k = i & (Hn - 1);
        V[r * KTOT + k] = ic[k];
    }
    // x[t=0] into buffer 0
    if (tid < 128) {
        int r = tid >> 5, j = tid & 31;
        const float4 xv = *reinterpret_cast<const float4*>(
            x + ((size_t)(rbase + r) * Tn) * Fn + 4 * j);
        *reinterpret_cast<float4*>(&V[r * KTOT + Hn + 4 * j]) = xv;
    }
    __syncthreads();
    cluster_sync_all();                       // barrier inits visible cluster-wide
    if (tid == 0) mbar_arrive_local(mb_full0); // pre-arm full[0] (phase 0, 0 tx)

    int phf0 = 0, phf1 = 0;

#define STEP_BODY(CUR, MBF_CUR, PHF_CUR, MBF_OTH, TT)                                  \
    {                                                                                   \
        float* vc = V + (CUR) * (ROWSn * KTOT);                                         \
        float* vn = V + ((CUR) ^ 1) * (ROWSn * KTOT);                                   \
        /* prefetch x[TT+1]; end-of-previous-step __syncthreads made vn-x free */       \
        if (tid < 128 && (TT) + 1 < Tn) {                                               \
            int r = tid >> 5, j = tid & 31;                                             \
            const float* src = x + ((size_t)(rbase + r) * Tn + ((TT) + 1)) * Fn + 4 * j;\
            unsigned dst = smem_u32(&vn[r * KTOT + Hn + 4 * j]);                        \
            asm volatile("cp.async.cg.shared.global [%0], [%1], 16;"                    \
                         :: "r"(dst), "l"(src));                                        \
            asm volatile("cp.async.commit_group;");                                     \
        }                                                                               \
        /* wait for the 7 peers' state slices (7168 tx bytes) */                        \
        mbar_wait_parity(MBF_CUR, (unsigned)(PHF_CUR)); (PHF_CUR) ^= 1;                 \
        /* GEMV partial, all fma.rn.f32x2 */                                            \
        const float* vkg = vc + kbase;                                                  \
        unsigned long long acc[ROWSn][4];                                               \
        _Pragma("unroll")                                                               \
        for (int r = 0; r < ROWSn; ++r)                                                 \
            { acc[r][0] = 0ULL; acc[r][1] = 0ULL; acc[r][2] = 0ULL; acc[r][3] = 0ULL; } \
        _Pragma("unroll")                                                               \
        for (int kb = 0; kb < KEXT / 4; ++kb) {                                         \
            const unsigned long long wA0 = w2[2 * kb][0],     wA1 = w2[2 * kb][1];      \
            const unsigned long long wA2 = w2[2 * kb][2],     wA3 = w2[2 * kb][3];      \
            const unsigned long long wB0 = w2[2 * kb + 1][0], wB1 = w2[2 * kb + 1][1];  \
            const unsigned long long wB2 = w2[2 * kb + 1][2], wB3 = w2[2 * kb + 1][3];  \
            _Pragma("unroll")                                                           \
            for (int r = 0; r < ROWSn; ++r) {                                           \
                const ulonglong2 qq = *reinterpret_cast<const ulonglong2*>(             \
                    vkg + r * KTOT + kb * 4);                                           \
                fma2(acc[r][0], qq.x, wA0);                                             \
                fma2(acc[r][1], qq.x, wA1);                                             \
                fma2(acc[r][2], qq.x, wA2);                                             \
                fma2(acc[r][3], qq.x, wA3);                                             \
                fma2(acc[r][0], qq.y, wB0);                                             \
                fma2(acc[r][1], qq.y, wB1);                                             \
                fma2(acc[r][2], qq.y, wB2);                                             \
                fma2(acc[r][3], qq.y, wB3);                                             \
            }                                                                           \
        }                                                                               \
        /* butterfly reduce over the 16-lane group: 15 SHFL, lane g ends with v=g */    \
        float red[16];                                                                  \
        _Pragma("unroll")                                                               \
        for (int v = 0; v < 16; ++v) red[v] = sum2(acc[v >> 2][v & 3]);                 \
        _Pragma("unroll")                                                               \
        for (int b = 8; b >= 1; b >>= 1) {                                              \
            const bool hi = (lane & b) != 0;                                            \
            _Pragma("unroll")                                                           \
            for (int u = 0; u < b; ++u) {                                               \
                float send = hi ? red[u] : red[u + b];                                  \
                float recv = __shfl_xor_sync(0xffffffffu, send, b);                     \
                red[u] = (hi ? red[u + b] : red[u]) + recv;                             \
            }                                                                           \
        }                                                                               \
        /* finalize my single output (r=fr, col=fhh) */                                 \
        const float sold = vc[fr * KTOT + hbase + fhh];                                 \
        float pre = red[0] + bi;                                                        \
        float th  = tanhf(pre);                                                         \
        float sn  = sold + dti * (th - sold);                                           \
        if (tid == 0) mbar_expect_tx(MBF_OTH, PEER_BYTES);                              \
        /* own slice locally (published by the bar); peers via st.async */              \
        vn[fr * KTOT + hbase + fhh] = sn;                                               \
        {                                                                               \
            unsigned my = smem_u32(&vn[fr * KTOT + hbase + fhh]);                       \
            _Pragma("unroll")                                                           \
            for (int c = 0; c < CLUSTER; ++c) {                                         \
                if (c != rank) st_async_remote(my, MBF_OTH, (unsigned)c, sn);           \
            }                                                                           \
        }                                                                               \
        if (tid < 128) { asm volatile("cp.async.wait_group 0;"); }                      \
        __syncthreads();  /* publish x[TT+1] + own slice; bound warp skew */            \
    }

    for (int t = 0; t < Tn; t += 2) {
        STEP_BODY(0, mb_full0, phf0, mb_full1, t)
        STEP_BODY(1, mb_full1, phf1, mb_full0, t + 1)
    }
#undef STEP_BODY

    // last step pushed into buffer 0 signaling full0 — needed for the readout
    mbar_wait_parity(mb_full0, (unsigned)phf0);

    // ---------------- readout (rank 0 of each cluster) ----------------
    if (rank == 0 && tid < ROWSn * On) {
        const int r = tid / On, o = tid - On * r;
        const float* s = V + r * KTOT;           // buffer 0
        float c0 = 0.f, c1 = 0.f, c2 = 0.f, c3 = 0.f;
        #pragma unroll 8
        for (int k = 0; k < Hn; k += 4) {
            c0 = fmaf(s[k    ], rw[(k    ) * On + o], c0);
            c1 = fmaf(s[k + 1], rw[(k + 1) * On + o], c1);
            c2 = fmaf(s[k + 2], rw[(k + 2) * On + o], c2);
            c3 = fmaf(s[k + 3], rw[(k + 3) * On + o], c3);
        }
        out[(rbase + r) * On + o] = (c0 + c1) + (c2 + c3) + rb[o];
    }

    cluster_sync_all();   // no CTA exits while peers' DSMEM traffic may be in flight
}

extern "C" void kernel_launch(void* const* d_in, const int* in_sizes, int n_in,
                              void* d_out, int out_size) {
    const float* x    = (const float*)d_in[0];
    const float* ic   = (const float*)d_in[1];
    const float* Win  = (const float*)d_in[2];
    const float* Wrec = (const float*)d_in[3];
    const float* b    = (const float*)d_in[4];
    const float* tau  = (const float*)d_in[5];
    const float* rw   = (const float*)d_in[6];
    const float* rb   = (const float*)d_in[7];
    float* out = (float*)d_out;

    cudaFuncSetAttribute(ctrnn_kernel,
                         cudaFuncAttributeMaxDynamicSharedMemorySize, SMEM_BYTES);
    ctrnn_kernel<<<(Bn / ROWSn) * CLUSTER, NT, SMEM_BYTES>>>(
        x, ic, Win, Wrec, b, tau, rw, rb, out);
}

// round 12
// speedup vs baseline: 1.3575x; 1.3575x over previous
#include <cuda_runtime.h>

// Problem constants
#define Bn 64
#define Tn 4096
#define Fn 128
#define Hn 512
#define On 10
#define DTc 0.1f

// 16 clusters x 8 CTAs; cluster owns 4 batch rows; CTA owns 64 H-columns.
// Weights register-resident (f32x2-packed). Broadcast q loads (kg = tid>>4).
// Cross-CTA exchange: st.async + tx-counted full barriers ONLY — backpressure
// is carried by the tx-counted data dependency (no empty barriers, no per-step
// remote arrives). Per step: one full-wait, one __syncthreads, 8 st.async.
#define CLUSTER 8
#define ROWSn 4
#define COLSn 64
#define KTOT 640           // Hn + Fn
#define NT 256
#define KEXT 40            // k-extent per thread
#define NKG 16
#define KP2 (KEXT / 2)

#define XCHG_BYTES (ROWSn * Hn * 4)   // 8192 B received per CTA per step (8 CTAs incl. self)

// SMEM layout (floats)
#define OFF_V 0                            // double-buffered [s(512);x(128)] per row
#define SZ_V (2 * ROWSn * KTOT)            // 5120
#define OFF_P (OFF_V + SZ_V)               // partials [r][kg][hh]
#define SZ_P (ROWSn * NKG * COLSn)         // 4096
#define OFF_B (OFF_P + SZ_P)
#define OFF_D (OFF_B + COLSn)
#define OFF_MB (OFF_D + COLSn)             // full0, full1 mbarriers
#define SMEM_FLOATS (OFF_MB + 4)
#define SMEM_BYTES (SMEM_FLOATS * 4)

__device__ __forceinline__ unsigned smem_u32(const void* p) {
    return (unsigned)__cvta_generic_to_shared(p);
}

__device__ __forceinline__ void cluster_sync_all() {
    asm volatile("barrier.cluster.arrive.aligned;\n\t"
                 "barrier.cluster.wait.aligned;" ::: "memory");
}

__device__ __forceinline__ unsigned long long pack2(float lo, float hi) {
    unsigned long long p;
    asm("mov.b64 %0, {%1, %2};" : "=l"(p) : "f"(lo), "f"(hi));
    return p;
}

__device__ __forceinline__ void fma2(unsigned long long& acc,
                                     unsigned long long q,
                                     unsigned long long w) {
    asm("fma.rn.f32x2 %0, %1, %2, %0;" : "+l"(acc) : "l"(q), "l"(w));
}

__device__ __forceinline__ float sum2(unsigned long long p) {
    float lo, hi;
    asm("mov.b64 {%0, %1}, %2;" : "=f"(lo), "=f"(hi) : "l"(p));
    return lo + hi;
}

// ---- mbarrier helpers ----
__device__ __forceinline__ void mbar_init(unsigned a, unsigned cnt) {
    asm volatile("mbarrier.init.shared.b64 [%0], %1;" :: "r"(a), "r"(cnt) : "memory");
}
__device__ __forceinline__ void mbar_arrive_local(unsigned a) {
    asm volatile("mbarrier.arrive.shared.b64 _, [%0];" :: "r"(a) : "memory");
}
__device__ __forceinline__ void mbar_expect_tx(unsigned a, unsigned bytes) {
    asm volatile("mbarrier.arrive.expect_tx.shared.b64 _, [%0], %1;"
                 :: "r"(a), "r"(bytes) : "memory");
}
__device__ __forceinline__ void mbar_wait_parity(unsigned a, unsigned ph) {
    asm volatile(
        "{\n\t.reg .pred P1;\n\t"
        "WAIT_LOOP_%=:\n\t"
        "mbarrier.try_wait.parity.acquire.cta.shared::cta.b64 P1, [%0], %1, 0x989680;\n\t"
        "@P1 bra.uni WAIT_DONE_%=;\n\t"
        "bra.uni WAIT_LOOP_%=;\n\t"
        "WAIT_DONE_%=:\n\t}"
        :: "r"(a), "r"(ph) : "memory");
}
// store 4B into rank's smem, signaling rank's mbarrier with 4 tx bytes
__device__ __forceinline__ void st_async_remote(unsigned local_data_addr,
                                                unsigned local_mbar_addr,
                                                unsigned rank, float v) {
    asm volatile("{\n\t.reg .b32 ra, rb;\n\t"
                 "mapa.shared::cluster.u32 ra, %0, %2;\n\t"
                 "mapa.shared::cluster.u32 rb, %1, %2;\n\t"
                 "st.async.shared::cluster.mbarrier::complete_tx::bytes.f32 [ra], %3, [rb];\n\t}"
                 :: "r"(local_data_addr), "r"(local_mbar_addr), "r"(rank), "f"(v)
                 : "memory");
}

extern __shared__ float smem[];

__global__ void __launch_bounds__(NT, 1) __cluster_dims__(CLUSTER, 1, 1)
ctrnn_kernel(const float* __restrict__ x, const float* __restrict__ ic,
             const float* __restrict__ Win, const float* __restrict__ Wrec,
             const float* __restrict__ bias, const float* __restrict__ tau,
             const float* __restrict__ rw, const float* __restrict__ rb,
             float* __restrict__ out)
{
    const int tid = threadIdx.x;
    const int rank = (int)(blockIdx.x & (CLUSTER - 1));
    const int clid = (int)(blockIdx.x >> 3);
    const int hbase = rank * COLSn;
    const int rbase = clid * ROWSn;

    float* V  = smem + OFF_V;    // 2 x [ROWSn][KTOT]
    float* P  = smem + OFF_P;    // [r][kg][hh]
    float* Bs = smem + OFF_B;
    float* Di = smem + OFF_D;

    const unsigned mb_full0 = smem_u32(smem + OFF_MB);
    const unsigned mb_full1 = mb_full0 + 8;

    // BROADCAST mapping (load-bearing): all 16 lanes of a half-warp share kg.
    const int kg = tid >> 4;             // 0..15 k-group
    const int cg = tid & 15;             // 0..15 col-group (4 cols)
    const int kbase = kg * KEXT;
    const int cbase = hbase + cg * 4;

    // ---- register weight tile, k-pair packed ----
    unsigned long long w2[KP2][4];
    #pragma unroll
    for (int kk2 = 0; kk2 < KP2; ++kk2) {
        const int k = kbase + 2 * kk2;
        const float* s0 = (k < Hn) ? (Wrec + (size_t)k * Hn + cbase)
                                   : (Win + (size_t)(k - Hn) * Hn + cbase);
        const float* s1 = (k + 1 < Hn) ? (Wrec + (size_t)(k + 1) * Hn + cbase)
                                       : (Win + (size_t)(k + 1 - Hn) * Hn + cbase);
        float4 a = *reinterpret_cast<const float4*>(s0);
        float4 b = *reinterpret_cast<const float4*>(s1);
        w2[kk2][0] = pack2(a.x, b.x);
        w2[kk2][1] = pack2(a.y, b.y);
        w2[kk2][2] = pack2(a.z, b.z);
        w2[kk2][3] = pack2(a.w, b.w);
    }

    if (tid == 0) {
        mbar_init(mb_full0, 1);
        mbar_init(mb_full1, 1);
        asm volatile("fence.mbarrier_init.release.cluster;" ::: "memory");
    }
    if (tid < COLSn) {
        Bs[tid] = bias[hbase + tid];
        Di[tid] = DTc / tau[hbase + tid];
    }
    for (int i = tid; i < ROWSn * Hn; i += NT) {
        int r = i >> 9, k = i & (Hn - 1);
        V[r * KTOT + k] = ic[k];
    }
    if (tid < 128) {
        int r = tid >> 5, j = tid & 31;
        const float4 xv = *reinterpret_cast<const float4*>(
            x + ((size_t)(rbase + r) * Tn) * Fn + 4 * j);
        *reinterpret_cast<float4*>(&V[r * KTOT + Hn + 4 * j]) = xv;
    }
    __syncthreads();

    const int fr = tid >> 6;
    const int fh = tid & 63;
    const float bi  = Bs[fh];
    const float dti = Di[fh];

    cluster_sync_all();                        // barrier inits visible cluster-wide
    if (tid == 0) mbar_arrive_local(mb_full0); // pre-arm full[0] (phase 0, 0 tx)

    int phf0 = 0, phf1 = 0;

#define STEP_BODY(CUR, MBF_CUR, PHF_CUR, MBF_OTH, TT)                                  \
    {                                                                                   \
        float* vc = V + (CUR) * (ROWSn * KTOT);                                         \
        float* vn = V + ((CUR) ^ 1) * (ROWSn * KTOT);                                   \
        /* prefetch x[TT+1] into vn (x region untouched by pushes) */                   \
        if (tid < 128 && (TT) + 1 < Tn) {                                               \
            int r = tid >> 5, j = tid & 31;                                             \
            const float* src = x + ((size_t)(rbase + r) * Tn + ((TT) + 1)) * Fn + 4 * j;\
            unsigned dst = smem_u32(&vn[r * KTOT + Hn + 4 * j]);                        \
            asm volatile("cp.async.cg.shared.global [%0], [%1], 16;"                    \
                         :: "r"(dst), "l"(src));                                        \
            asm volatile("cp.async.commit_group;");                                     \
        }                                                                               \
        /* wait for all 8192 exchange bytes of this step's input state */               \
        mbar_wait_parity(MBF_CUR, (unsigned)(PHF_CUR)); (PHF_CUR) ^= 1;                 \
        /* GEMV partial, all fma.rn.f32x2, broadcast q loads */                         \
        const float* vkg = vc + kbase;                                                  \
        unsigned long long acc[ROWSn][4];                                               \
        _Pragma("unroll")                                                               \
        for (int r = 0; r < ROWSn; ++r)                                                 \
            { acc[r][0] = 0ULL; acc[r][1] = 0ULL; acc[r][2] = 0ULL; acc[r][3] = 0ULL; } \
        _Pragma("unroll")                                                               \
        for (int kb = 0; kb < KEXT / 4; ++kb) {                                         \
            const unsigned long long wA0 = w2[2 * kb][0],     wA1 = w2[2 * kb][1];      \
            const unsigned long long wA2 = w2[2 * kb][2],     wA3 = w2[2 * kb][3];      \
            const unsigned long long wB0 = w2[2 * kb + 1][0], wB1 = w2[2 * kb + 1][1];  \
            const unsigned long long wB2 = w2[2 * kb + 1][2], wB3 = w2[2 * kb + 1][3];  \
            _Pragma("unroll")                                                           \
            for (int r = 0; r < ROWSn; ++r) {                                           \
                const ulonglong2 qq = *reinterpret_cast<const ulonglong2*>(             \
                    vkg + r * KTOT + kb * 4);                                           \
                fma2(acc[r][0], qq.x, wA0);                                             \
                fma2(acc[r][1], qq.x, wA1);                                             \
                fma2(acc[r][2], qq.x, wA2);                                             \
                fma2(acc[r][3], qq.x, wA3);                                             \
                fma2(acc[r][0], qq.y, wB0);                                             \
                fma2(acc[r][1], qq.y, wB1);                                             \
                fma2(acc[r][2], qq.y, wB2);                                             \
                fma2(acc[r][3], qq.y, wB3);                                             \
            }                                                                           \
        }                                                                               \
        /* sold read before pushes (push is this thread's last access to vc) */         \
        const float sold = vc[fr * KTOT + hbase + fh];                                  \
        _Pragma("unroll")                                                               \
        for (int r = 0; r < ROWSn; ++r) {                                               \
            *reinterpret_cast<float4*>(&P[(r * NKG + kg) * COLSn + cg * 4]) =           \
                make_float4(sum2(acc[r][0]), sum2(acc[r][1]),                           \
                            sum2(acc[r][2]), sum2(acc[r][3]));                          \
        }                                                                               \
        if (tid < 128) { asm volatile("cp.async.wait_group 0;"); }                      \
        __syncthreads();  /* publish P and x[TT+1] */                                   \
        /* reduce 16 partials, finalize */                                              \
        const float* pr = &P[fr * NKG * COLSn + fh];                                    \
        float s0 = 0.f, s1 = 0.f;                                                       \
        _Pragma("unroll")                                                               \
        for (int g = 0; g < NKG; g += 2) {                                              \
            s0 += pr[g * COLSn];                                                        \
            s1 += pr[(g + 1) * COLSn];                                                  \
        }                                                                               \
        float pre = (s0 + s1) + bi;                                                     \
        float th  = tanhf(pre);                                                         \
        float sn  = sold + dti * (th - sold);                                           \
        if (tid == 0) mbar_expect_tx(MBF_OTH, XCHG_BYTES);                              \
        /* push s' to all 8 CTAs (incl. self), tx-counted on their full barrier */      \
        {                                                                               \
            unsigned my = smem_u32(&vn[fr * KTOT + hbase + fh]);                        \
            _Pragma("unroll")                                                           \
            for (int c = 0; c < CLUSTER; ++c)                                           \
                st_async_remote(my, MBF_OTH, (unsigned)c, sn);                          \
        }                                                                               \
    }

    for (int t = 0; t < Tn; t += 2) {
        STEP_BODY(0, mb_full0, phf0, mb_full1, t)
        STEP_BODY(1, mb_full1, phf1, mb_full0, t + 1)
    }
#undef STEP_BODY

    // last step pushed into buffer 0 signaling full0 — needed for the readout
    mbar_wait_parity(mb_full0, (unsigned)phf0);

    // ---------------- readout (rank 0 of each cluster) ----------------
    if (rank == 0 && tid < ROWSn * On) {
        const int r = tid / On, o = tid - On * r;
        const float* s = V + r * KTOT;           // buffer 0
        float c0 = 0.f, c1 = 0.f, c2 = 0.f, c3 = 0.f;
        #pragma unroll 8
        for (int k = 0; k < Hn; k += 4) {
            c0 = fmaf(s[k    ], rw[(k    ) * On + o], c0);
            c1 = fmaf(s[k + 1], rw[(k + 1) * On + o], c1);
            c2 = fmaf(s[k + 2], rw[(k + 2) * On + o], c2);
            c3 = fmaf(s[k + 3], rw[(k + 3) * On + o], c3);
        }
        out[(rbase + r) * On + o] = (c0 + c1) + (c2 + c3) + rb[o];
    }

    cluster_sync_all();   // no CTA exits while peers' DSMEM traffic may be in flight
}

extern "C" void kernel_launch(void* const* d_in, const int* in_sizes, int n_in,
                              void* d_out, int out_size) {
    const float* x    = (const float*)d_in[0];
    const float* ic   = (const float*)d_in[1];
    const float* Win  = (const float*)d_in[2];
    const float* Wrec = (const float*)d_in[3];
    const float* b    = (const float*)d_in[4];
    const float* tau  = (const float*)d_in[5];
    const float* rw   = (const float*)d_in[6];
    const float* rb   = (const float*)d_in[7];
    float* out = (float*)d_out;

    cudaFuncSetAttribute(ctrnn_kernel,
                         cudaFuncAttributeMaxDynamicSharedMemorySize, SMEM_BYTES);
    ctrnn_kernel<<<(Bn / ROWSn) * CLUSTER, NT, SMEM_BYTES>>>(
        x, ic, Win, Wrec, b, tau, rw, rb, out);
}

// round 16
// speedup vs baseline: 1.4151x; 1.0424x over previous
#include <cuda_runtime.h>

// Problem constants
#define Bn 64
#define Tn 4096
#define Fn 128
#define Hn 512
#define On 10
#define DTc 0.1f

// 16 clusters x 8 CTAs; cluster owns 4 batch rows; CTA owns 64 H-columns.
// PROVEN 10.63ms structure (round-7 pass): weights register-resident
// (f32x2-packed), broadcast q loads, st.async f32 exchange with tx-counted
// full barriers + empty-barrier backpressure ring. Single change this round:
// tanhf -> tanh_fast (ex2.approx+rcp.approx) on the critical path.
#define CLUSTER 8
#define ROWSn 4
#define COLSn 64
#define KTOT 640           // Hn + Fn
#define NT 256
#define KEXT 40            // k-extent per thread
#define NKG 16
#define KP2 (KEXT / 2)

#define XCHG_BYTES (ROWSn * Hn * 4)   // 8192 B received per CTA per step

// SMEM layout (floats)
#define OFF_V 0                            // double-buffered [s(512);x(128)] per row
#define SZ_V (2 * ROWSn * KTOT)            // 5120
#define OFF_P (OFF_V + SZ_V)               // partials [r][kg][hh]
#define SZ_P (ROWSn * NKG * COLSn)         // 4096
#define OFF_B (OFF_P + SZ_P)
#define OFF_D (OFF_B + COLSn)
#define OFF_MB (OFF_D + COLSn)             // full0,full1,empty0,empty1 mbarriers
#define SMEM_FLOATS (OFF_MB + 8)
#define SMEM_BYTES (SMEM_FLOATS * 4)

__device__ __forceinline__ unsigned smem_u32(const void* p) {
    return (unsigned)__cvta_generic_to_shared(p);
}

__device__ __forceinline__ void cluster_sync_all() {
    asm volatile("barrier.cluster.arrive.aligned;\n\t"
                 "barrier.cluster.wait.aligned;" ::: "memory");
}

__device__ __forceinline__ unsigned long long pack2(float lo, float hi) {
    unsigned long long p;
    asm("mov.b64 %0, {%1, %2};" : "=l"(p) : "f"(lo), "f"(hi));
    return p;
}

__device__ __forceinline__ void fma2(unsigned long long& acc,
                                     unsigned long long q,
                                     unsigned long long w) {
    asm("fma.rn.f32x2 %0, %1, %2, %0;" : "+l"(acc) : "l"(q), "l"(w));
}

__device__ __forceinline__ float sum2(unsigned long long p) {
    float lo, hi;
    asm("mov.b64 {%0, %1}, %2;" : "=f"(lo), "=f"(hi) : "l"(p));
    return lo + hi;
}

// fast tanh: 1 - 2/(exp2(2x*log2e)+1); saturates correctly, ~1e-6 rel err
__device__ __forceinline__ float tanh_fast(float x) {
    float e;
    asm("ex2.approx.ftz.f32 %0, %1;" : "=f"(e) : "f"(x * 2.8853900817779268f));
    float r;
    asm("rcp.approx.ftz.f32 %0, %1;" : "=f"(r) : "f"(e + 1.0f));
    return fmaf(-2.0f, r, 1.0f);
}

// ---- mbarrier helpers ----
__device__ __forceinline__ void mbar_init(unsigned a, unsigned cnt) {
    asm volatile("mbarrier.init.shared.b64 [%0], %1;" :: "r"(a), "r"(cnt) : "memory");
}
__device__ __forceinline__ void mbar_arrive_local(unsigned a) {
    asm volatile("mbarrier.arrive.shared.b64 _, [%0];" :: "r"(a) : "memory");
}
__device__ __forceinline__ void mbar_arrive_remote(unsigned local_addr, unsigned rank) {
    asm volatile("{\n\t.reg .b32 ra;\n\t"
                 "mapa.shared::cluster.u32 ra, %0, %1;\n\t"
                 "mbarrier.arrive.shared::cluster.b64 _, [ra];\n\t}"
                 :: "r"(local_addr), "r"(rank) : "memory");
}
__device__ __forceinline__ void mbar_expect_tx(unsigned a, unsigned bytes) {
    asm volatile("mbarrier.arrive.expect_tx.shared.b64 _, [%0], %1;"
                 :: "r"(a), "r"(bytes) : "memory");
}
__device__ __forceinline__ void mbar_wait_parity(unsigned a, unsigned ph) {
    asm volatile(
        "{\n\t.reg .pred P1;\n\t"
        "WAIT_LOOP_%=:\n\t"
        "mbarrier.try_wait.parity.acquire.cta.shared::cta.b64 P1, [%0], %1, 0x989680;\n\t"
        "@P1 bra.uni WAIT_DONE_%=;\n\t"
        "bra.uni WAIT_LOOP_%=;\n\t"
        "WAIT_DONE_%=:\n\t}"
        :: "r"(a), "r"(ph) : "memory");
}
// store 4B into rank's smem, signaling rank's mbarrier with 4 tx bytes
__device__ __forceinline__ void st_async_remote(unsigned local_data_addr,
                                                unsigned local_mbar_addr,
                                                unsigned rank, float v) {
    asm volatile("{\n\t.reg .b32 ra, rb;\n\t"
                 "mapa.shared::cluster.u32 ra, %0, %2;\n\t"
                 "mapa.shared::cluster.u32 rb, %1, %2;\n\t"
                 "st.async.shared::cluster.mbarrier::complete_tx::bytes.f32 [ra], %3, [rb];\n\t}"
                 :: "r"(local_data_addr), "r"(local_mbar_addr), "r"(rank), "f"(v)
                 : "memory");
}

extern __shared__ float smem[];

__global__ void __launch_bounds__(NT, 1) __cluster_dims__(CLUSTER, 1, 1)
ctrnn_kernel(const float* __restrict__ x, const float* __restrict__ ic,
             const float* __restrict__ Win, const float* __restrict__ Wrec,
             const float* __restrict__ bias, const float* __restrict__ tau,
             const float* __restrict__ rw, const float* __restrict__ rb,
             float* __restrict__ out)
{
    const int tid = threadIdx.x;
    const int rank = (int)(blockIdx.x & (CLUSTER - 1));
    const int clid = (int)(blockIdx.x >> 3);
    const int hbase = rank * COLSn;
    const int rbase = clid * ROWSn;

    float* V  = smem + OFF_V;    // 2 x [ROWSn][KTOT]
    float* P  = smem + OFF_P;    // [r][kg][hh]
    float* Bs = smem + OFF_B;
    float* Di = smem + OFF_D;

    const unsigned mb_base   = smem_u32(smem + OFF_MB);
    const unsigned mb_full0  = mb_base;
    const unsigned mb_full1  = mb_base + 8;
    const unsigned mb_empty0 = mb_base + 16;
    const unsigned mb_empty1 = mb_base + 24;

    // BROADCAST mapping (load-bearing): all 16 lanes of a half-warp share kg.
    const int kg = tid >> 4;             // 0..15 k-group
    const int cg = tid & 15;             // 0..15 col-group (4 cols)
    const int kbase = kg * KEXT;
    const int cbase = hbase + cg * 4;

    // ---- register weight tile, k-pair packed ----
    unsigned long long w2[KP2][4];
    #pragma unroll
    for (int kk2 = 0; kk2 < KP2; ++kk2) {
        const int k = kbase + 2 * kk2;
        const float* s0 = (k < Hn) ? (Wrec + (size_t)k * Hn + cbase)
                                   : (Win + (size_t)(k - Hn) * Hn + cbase);
        const float* s1 = (k + 1 < Hn) ? (Wrec + (size_t)(k + 1) * Hn + cbase)
                                       : (Win + (size_t)(k + 1 - Hn) * Hn + cbase);
        float4 a = *reinterpret_cast<const float4*>(s0);
        float4 b = *reinterpret_cast<const float4*>(s1);
        w2[kk2][0] = pack2(a.x, b.x);
        w2[kk2][1] = pack2(a.y, b.y);
        w2[kk2][2] = pack2(a.z, b.z);
        w2[kk2][3] = pack2(a.w, b.w);
    }

    if (tid == 0) {
        mbar_init(mb_full0, 1);
        mbar_init(mb_full1, 1);
        mbar_init(mb_empty0, CLUSTER);
        mbar_init(mb_empty1, CLUSTER);
        asm volatile("fence.mbarrier_init.release.cluster;" ::: "memory");
    }
    if (tid < COLSn) {
        Bs[tid] = bias[hbase + tid];
        Di[tid] = DTc / tau[hbase + tid];
    }
    for (int i = tid; i < ROWSn * Hn; i += NT) {
        int r = i >> 9, k = i & (Hn - 1);
        V[r * KTOT + k] = ic[k];
    }
    if (tid < 128) {
        int r = tid >> 5, j = tid & 31;
        const float4 xv = *reinterpret_cast<const float4*>(
            x + ((size_t)(rbase + r) * Tn) * Fn + 4 * j);
        *reinterpret_cast<float4*>(&V[r * KTOT + Hn + 4 * j]) = xv;
    }
    __syncthreads();

    const int fr = tid >> 6;
    const int fh = tid & 63;
    const float bi  = Bs[fh];
    const float dti = Di[fh];

    cluster_sync_all();          // all inits visible cluster-wide
    if (tid == 0) {
        mbar_arrive_local(mb_full0);                  // pre-arm full[0] (phase 0)
        #pragma unroll
        for (int c = 0; c < CLUSTER; ++c)
            mbar_arrive_remote(mb_empty1, (unsigned)c); // pre-arm empty[1]
    }

    int phf0 = 0, phf1 = 0, phe0 = 0, phe1 = 0;

#define STEP_BODY(CUR, MBF_CUR, PHF_CUR, MBE_CUR, MBE_OTH, PHE_OTH, MBF_OTH, TT)       \
    {                                                                                   \
        float* vc = V + (CUR) * (ROWSn * KTOT);                                         \
        float* vn = V + ((CUR) ^ 1) * (ROWSn * KTOT);                                   \
        /* prefetch x[TT+1] into vn (published by this step's __syncthreads) */         \
        if (tid < 128 && (TT) + 1 < Tn) {                                               \
            int r = tid >> 5, j = tid & 31;                                             \
            const float* src = x + ((size_t)(rbase + r) * Tn + ((TT) + 1)) * Fn + 4 * j;\
            unsigned dst = smem_u32(&vn[r * KTOT + Hn + 4 * j]);                        \
            asm volatile("cp.async.cg.shared.global [%0], [%1], 16;"                    \
                         :: "r"(dst), "l"(src));                                        \
            asm volatile("cp.async.commit_group;");                                     \
        }                                                                               \
        /* wait for this step's input state (all 8192 exchange bytes landed) */         \
        mbar_wait_parity(MBF_CUR, (unsigned)(PHF_CUR)); (PHF_CUR) ^= 1;                 \
        /* GEMV partial, all fma.rn.f32x2 */                                            \
        const float* vkg = vc + kbase;                                                  \
        unsigned long long acc[ROWSn][4];                                               \
        _Pragma("unroll")                                                               \
        for (int r = 0; r < ROWSn; ++r)                                                 \
            { acc[r][0] = 0ULL; acc[r][1] = 0ULL; acc[r][2] = 0ULL; acc[r][3] = 0ULL; } \
        _Pragma("unroll")                                                               \
        for (int kb = 0; kb < KEXT / 4; ++kb) {                                         \
            const unsigned long long wA0 = w2[2 * kb][0],     wA1 = w2[2 * kb][1];      \
            const unsigned long long wA2 = w2[2 * kb][2],     wA3 = w2[2 * kb][3];      \
            const unsigned long long wB0 = w2[2 * kb + 1][0], wB1 = w2[2 * kb + 1][1];  \
            const unsigned long long wB2 = w2[2 * kb + 1][2], wB3 = w2[2 * kb + 1][3];  \
            _Pragma("unroll")                                                           \
            for (int r = 0; r < ROWSn; ++r) {                                           \
                const ulonglong2 qq = *reinterpret_cast<const ulonglong2*>(             \
                    vkg + r * KTOT + kb * 4);                                           \
                fma2(acc[r][0], qq.x, wA0);                                             \
                fma2(acc[r][1], qq.x, wA1);                                             \
                fma2(acc[r][2], qq.x, wA2);                                             \
                fma2(acc[r][3], qq.x, wA3);                                             \
                fma2(acc[r][0], qq.y, wB0);                                             \
                fma2(acc[r][1], qq.y, wB1);                                             \
                fma2(acc[r][2], qq.y, wB2);                                             \
                fma2(acc[r][3], qq.y, wB3);                                             \
            }                                                                           \
        }                                                                               \
        /* sold read before __syncthreads (peers may overwrite vc after our */          \
        /* empty[CUR] arrive below) */                                                  \
        const float sold = vc[fr * KTOT + hbase + fh];                                  \
        _Pragma("unroll")                                                               \
        for (int r = 0; r < ROWSn; ++r) {                                               \
            *reinterpret_cast<float4*>(&P[(r * NKG + kg) * COLSn + cg * 4]) =           \
                make_float4(sum2(acc[r][0]), sum2(acc[r][1]),                           \
                            sum2(acc[r][2]), sum2(acc[r][3]));                          \
        }                                                                               \
        if (tid < 128) { asm volatile("cp.async.wait_group 0;"); }                      \
        __syncthreads();                                                                \
        /* all warps done reading vc -> tell everyone this buffer is consumable */      \
        if (tid == 0) {                                                                 \
            _Pragma("unroll")                                                           \
            for (int c = 0; c < CLUSTER; ++c)                                           \
                mbar_arrive_remote(MBE_CUR, (unsigned)c);                               \
        }                                                                               \
        /* reduce partials, finalize */                                                 \
        const float* pr = &P[fr * NKG * COLSn + fh];                                    \
        float s0 = 0.f, s1 = 0.f;                                                       \
        _Pragma("unroll")                                                               \
        for (int g = 0; g < NKG; g += 2) {                                              \
            s0 += pr[g * COLSn];                                                        \
            s1 += pr[(g + 1) * COLSn];                                                  \
        }                                                                               \
        float pre = (s0 + s1) + bi;                                                     \
        float th  = tanh_fast(pre);                                                     \
        float sn  = sold + dti * (th - sold);                                           \
        /* backpressure: peers must have consumed the buffer we now overwrite */        \
        mbar_wait_parity(MBE_OTH, (unsigned)(PHE_OTH)); (PHE_OTH) ^= 1;                 \
        if (tid == 0) mbar_expect_tx(MBF_OTH, XCHG_BYTES);                              \
        /* push s' to all 8 CTAs (incl. self), tx-counted on their full barrier */      \
        {                                                                               \
            unsigned my = smem_u32(&vn[fr * KTOT + hbase + fh]);                        \
            _Pragma("unroll")                                                           \
            for (int c = 0; c < CLUSTER; ++c)                                           \
                st_async_remote(my, MBF_OTH, (unsigned)c, sn);                          \
        }                                                                               \
    }

    for (int t = 0; t < Tn; t += 2) {
        STEP_BODY(0, mb_full0, phf0, mb_empty0, mb_empty1, phe1, mb_full1, t)
        STEP_BODY(1, mb_full1, phf1, mb_empty1, mb_empty0, phe0, mb_full0, t + 1)
    }
#undef STEP_BODY

    // final exchange (last step stored into buffer 0, signaling full[0])
    mbar_wait_parity(mb_full0, (unsigned)phf0);

    // ---------------- readout (rank 0 of each cluster) ----------------
    if (rank == 0 && tid < ROWSn * On) {
        const int r = tid / On, o = tid - On * r;
        const float* s = V + r * KTOT;           // buffer 0
        float c0 = 0.f, c1 = 0.f, c2 = 0.f, c3 = 0.f;
        #pragma unroll 8
        for (int k = 0; k < Hn; k += 4) {
            c0 = fmaf(s[k    ], rw[(k    ) * On + o], c0);
            c1 = fmaf(s[k + 1], rw[(k + 1) * On + o], c1);
            c2 = fmaf(s[k + 2], rw[(k + 2) * On + o], c2);
            c3 = fmaf(s[k + 3], rw[(k + 3) * On + o], c3);
        }
        out[(rbase + r) * On + o] = (c0 + c1) + (c2 + c3) + rb[o];
    }

    cluster_sync_all();   // no CTA exits while peers' DSMEM traffic may be in flight
}

extern "C" void kernel_launch(void* const* d_in, const int* in_sizes, int n_in,
                              void* d_out, int out_size) {
    const float* x    = (const float*)d_in[0];
    const float* ic   = (const float*)d_in[1];
    const float* Win  = (const float*)d_in[2];
    const float* Wrec = (const float*)d_in[3];
    const float* b    = (const float*)d_in[4];
    const float* tau  = (const float*)d_in[5];
    const float* rw   = (const float*)d_in[6];
    const float* rb   = (const float*)d_in[7];
    float* out = (float*)d_out;

    cudaFuncSetAttribute(ctrnn_kernel,
                         cudaFuncAttributeMaxDynamicSharedMemorySize, SMEM_BYTES);
    ctrnn_kernel<<<(Bn / ROWSn) * CLUSTER, NT, SMEM_BYTES>>>(
        x, ic, Win, Wrec, b, tau, rw, rb, out);
}